// round 1
// baseline (speedup 1.0000x reference)
#include <cuda_runtime.h>
#include <cuda_bf16.h>
#include <mma.h>

using namespace nvcuda;

#define BATCH 64
#define SEQ   512
#define HID   512
#define GATES 2048      // 4*HID
#define KIN   96        // 64 + 32
#define ODIM  128

#define NB_SCAN 128
#define NT_SCAN 128

// ---------------- static device scratch (no allocations allowed) ----------------
__device__ float g_xproj[(size_t)BATCH * SEQ * GATES];   // 256 MB, reused for layer0 then layer1
__device__ float g_h0s[(size_t)BATCH * SEQ * HID];       // 64 MB, layer-0 hidden history
__device__ float g_xcat[(size_t)BATCH * SEQ * KIN];      // 12 MB
__device__ float g_Wih0p[GATES * KIN];
__device__ float g_Whh0p[GATES * HID];
__device__ float g_Wih1p[GATES * HID];
__device__ float g_Whh1p[GATES * HID];
__device__ float g_biasP[2][GATES];
__device__ float g_hbuf[2][BATCH * HID];                 // ping-pong hidden state
__device__ float g_cst[BATCH * HID];                     // cell state
__device__ unsigned g_bar_count;
__device__ unsigned g_bar_gen;

// ---------------- grid barrier (sense via generation counter) ----------------
__device__ __forceinline__ void grid_barrier()
{
    __syncthreads();
    if (threadIdx.x == 0) {
        __threadfence();  // make my h/c writes visible before signaling
        unsigned gen = atomicAdd(&g_bar_gen, 0u);
        unsigned arrived = atomicAdd(&g_bar_count, 1u);
        if (arrived == NB_SCAN - 1) {
            atomicExch(&g_bar_count, 0u);
            __threadfence();
            atomicAdd(&g_bar_gen, 1u);
        } else {
            while (atomicAdd(&g_bar_gen, 0u) == gen) { __nanosleep(32); }
        }
        // gpu-scope fence -> CCTL.IVALL: invalidate this SM's L1D so the
        // subsequent loads of h (written by other SMs) are not stale.
        __threadfence();
    }
    __syncthreads();
}

__device__ __forceinline__ float sigm(float x) { return 1.0f / (1.0f + expf(-x)); }

// ---------------- prep: concat input, permute weights so gates interleave ----------------
// col' = 4*u + gate  <->  original row r = gate*HID + u
__global__ void prep_kernel(const float* __restrict__ prim, const float* __restrict__ aux,
                            const float* __restrict__ Wih0, const float* __restrict__ Whh0,
                            const float* __restrict__ bih0, const float* __restrict__ bhh0,
                            const float* __restrict__ Wih1, const float* __restrict__ Whh1,
                            const float* __restrict__ bih1, const float* __restrict__ bhh1)
{
    size_t tid = (size_t)blockIdx.x * blockDim.x + threadIdx.x;
    size_t nth = (size_t)gridDim.x * blockDim.x;

    for (size_t i = tid; i < (size_t)BATCH * SEQ * KIN; i += nth) {
        int k = (int)(i % KIN);
        size_t bt = i / KIN;
        int b = (int)(bt / SEQ);
        g_xcat[i] = (k < 64) ? prim[bt * 64 + k] : aux[b * 32 + (k - 64)];
    }
    for (size_t i = tid; i < (size_t)GATES * HID; i += nth) {
        int k  = (int)(i % HID);
        int cp = (int)(i / HID);
        int u = cp >> 2, gi = cp & 3;
        size_t r = (size_t)(gi * HID + u) * HID + k;
        g_Whh0p[i] = Whh0[r];
        g_Whh1p[i] = Whh1[r];
        g_Wih1p[i] = Wih1[r];
    }
    for (size_t i = tid; i < (size_t)GATES * KIN; i += nth) {
        int k  = (int)(i % KIN);
        int cp = (int)(i / KIN);
        int u = cp >> 2, gi = cp & 3;
        g_Wih0p[i] = Wih0[(size_t)(gi * HID + u) * KIN + k];
    }
    for (size_t i = tid; i < GATES; i += nth) {
        int u = (int)(i >> 2), gi = (int)(i & 3);
        int r = gi * HID + u;
        g_biasP[0][i] = bih0[r] + bhh0[r];
        g_biasP[1][i] = bih1[r] + bhh1[r];
    }
}

// ---------------- big parallel GEMM (tf32 wmma): C[32768 x 2048] = A[M x K] @ Wp^T ----------------
// phase 0: A = g_xcat   (K=96),  B = g_Wih0p
// phase 1: A = g_h0s    (K=512), B = g_Wih1p
#define GT_M 128
#define GT_N 128
#define KCHUNK 16
#define SPAD 20

__global__ void __launch_bounds__(256) gemm_tf32(int phase)
{
    __shared__ float As[GT_M * SPAD];
    __shared__ float Bs[GT_N * SPAD];

    const float* A  = phase ? g_h0s   : g_xcat;
    const float* Bm = phase ? g_Wih1p : g_Wih0p;
    const int K     = phase ? HID     : KIN;

    int tn = blockIdx.x;           // 0..15
    int tm = blockIdx.y;           // 0..255
    int tid = threadIdx.x;
    int wid = tid >> 5;
    int wm = wid >> 2, wn = wid & 3;   // warp grid 2 x 4, warp tile 64 x 32

    wmma::fragment<wmma::accumulator, 16, 16, 8, float> acc[4][2];
#pragma unroll
    for (int i = 0; i < 4; i++)
#pragma unroll
        for (int j = 0; j < 2; j++) wmma::fill_fragment(acc[i][j], 0.0f);

    const float* Abase = A  + (size_t)tm * GT_M * K;
    const float* Bbase = Bm + (size_t)tn * GT_N * K;

    for (int k0 = 0; k0 < K; k0 += KCHUNK) {
        __syncthreads();
#pragma unroll
        for (int s = tid; s < GT_M * 4; s += 256) {
            int m = s >> 2, q = s & 3;
            *(float4*)&As[m * SPAD + q * 4] = *(const float4*)&Abase[(size_t)m * K + k0 + q * 4];
            *(float4*)&Bs[m * SPAD + q * 4] = *(const float4*)&Bbase[(size_t)m * K + k0 + q * 4];
        }
        __syncthreads();
#pragma unroll
        for (int ks = 0; ks < 2; ks++) {
            wmma::fragment<wmma::matrix_b, 16, 16, 8, wmma::precision::tf32, wmma::col_major> bf[2];
#pragma unroll
            for (int j = 0; j < 2; j++) {
                wmma::load_matrix_sync(bf[j], &Bs[(wn * 32 + j * 16) * SPAD + ks * 8], SPAD);
#pragma unroll
                for (int e = 0; e < bf[j].num_elements; e++)
                    bf[j].x[e] = wmma::__float_to_tf32(bf[j].x[e]);
            }
#pragma unroll
            for (int i = 0; i < 4; i++) {
                wmma::fragment<wmma::matrix_a, 16, 16, 8, wmma::precision::tf32, wmma::row_major> af;
                wmma::load_matrix_sync(af, &As[(wm * 64 + i * 16) * SPAD + ks * 8], SPAD);
#pragma unroll
                for (int e = 0; e < af.num_elements; e++)
                    af.x[e] = wmma::__float_to_tf32(af.x[e]);
#pragma unroll
                for (int j = 0; j < 2; j++) wmma::mma_sync(acc[i][j], af, bf[j], acc[i][j]);
            }
        }
    }
#pragma unroll
    for (int i = 0; i < 4; i++)
#pragma unroll
        for (int j = 0; j < 2; j++) {
            int gm = tm * GT_M + wm * 64 + i * 16;
            int gn = tn * GT_N + wn * 32 + j * 16;
            wmma::store_matrix_sync(&g_xproj[(size_t)gm * GATES + gn], acc[i][j], GATES,
                                    wmma::mem_row_major);
        }
}

// ---------------- persistent recurrent scan (one layer) ----------------
// 128 CTAs x 128 threads. CTA c owns hidden units [4c, 4c+4) = gate cols [16c, 16c+16).
// warp w handles batch rows [16w, 16w+16). Full K=512 per warp (64 k-steps of 8).
__global__ void __launch_bounds__(NT_SCAN) scan_tf32(int layer)
{
    __shared__ float sg[4 * 256];
    const int c   = blockIdx.x;
    const int tid = threadIdx.x;
    const int w   = tid >> 5;

    const float* Wp    = layer ? g_Whh1p : g_Whh0p;
    const float* biasP = g_biasP[layer];

    // zero state (fresh every launch), then make it globally visible
    for (int i = blockIdx.x * NT_SCAN + tid; i < BATCH * HID; i += NB_SCAN * NT_SCAN) {
        g_cst[i] = 0.0f;
        g_hbuf[0][i] = 0.0f;
    }
    grid_barrier();

    const float* Wbase = Wp + (size_t)c * 16 * HID;

    for (int t = 0; t < SEQ; t++) {
        const float* hread  = g_hbuf[t & 1];
        float*       hwrite = g_hbuf[(t & 1) ^ 1];

        wmma::fragment<wmma::accumulator, 16, 16, 8, float> acc0, acc1;
        wmma::fill_fragment(acc0, 0.0f);
        wmma::fill_fragment(acc1, 0.0f);
        const float* Arow = hread + (size_t)w * 16 * HID;

#pragma unroll 4
        for (int ks = 0; ks < 64; ks += 2) {
            wmma::fragment<wmma::matrix_a, 16, 16, 8, wmma::precision::tf32, wmma::row_major> af0, af1;
            wmma::fragment<wmma::matrix_b, 16, 16, 8, wmma::precision::tf32, wmma::col_major> bf0, bf1;
            wmma::load_matrix_sync(af0, Arow + ks * 8, HID);
            wmma::load_matrix_sync(bf0, Wbase + ks * 8, HID);
            wmma::load_matrix_sync(af1, Arow + ks * 8 + 8, HID);
            wmma::load_matrix_sync(bf1, Wbase + ks * 8 + 8, HID);
#pragma unroll
            for (int e = 0; e < 4; e++) {
                af0.x[e] = wmma::__float_to_tf32(af0.x[e]);
                af1.x[e] = wmma::__float_to_tf32(af1.x[e]);
                bf0.x[e] = wmma::__float_to_tf32(bf0.x[e]);
                bf1.x[e] = wmma::__float_to_tf32(bf1.x[e]);
            }
            wmma::mma_sync(acc0, af0, bf0, acc0);
            wmma::mma_sync(acc1, af1, bf1, acc1);
        }
#pragma unroll
        for (int e = 0; e < acc0.num_elements; e++) acc0.x[e] += acc1.x[e];
        wmma::store_matrix_sync(&sg[w * 256], acc0, 16, wmma::mem_row_major);
        __syncthreads();

        // elementwise LSTM cell: 256 (b, unit) pairs, 2 per thread
#pragma unroll
        for (int rep = 0; rep < 2; rep++) {
            int p  = tid + rep * NT_SCAN;
            int b  = p >> 2;
            int ul = p & 3;
            const float* gp = &sg[(b >> 4) * 256 + (b & 15) * 16 + ul * 4];
            float4 xp = *(const float4*)(g_xproj + ((size_t)(b * SEQ + t)) * GATES + c * 16 + ul * 4);
            float4 bb = *(const float4*)(biasP + c * 16 + ul * 4);
            float pi = gp[0] + xp.x + bb.x;
            float pf = gp[1] + xp.y + bb.y;
            float pg = gp[2] + xp.z + bb.z;
            float po = gp[3] + xp.w + bb.w;
            float ig = sigm(pi), fg = sigm(pf), gg = tanhf(pg), og = sigm(po);
            int u   = c * 4 + ul;
            int idx = b * HID + u;
            float cn = fg * g_cst[idx] + ig * gg;
            g_cst[idx] = cn;
            float hv = og * tanhf(cn);
            hwrite[idx] = hv;
            if (layer == 0) g_h0s[((size_t)(b * SEQ + t)) * HID + u] = hv;
        }
        grid_barrier();
    }
}

// ---------------- output projection: out[b,o] = h_last[b,:] . W_out[o,:] + b_out[o] ----------------
__global__ void out_kernel(const float* __restrict__ Wout, const float* __restrict__ bout,
                           float* __restrict__ out)
{
    int b = blockIdx.x;    // 64
    int o = threadIdx.x;   // 128
    const float* h  = g_hbuf[0] + b * HID;   // SEQ even -> final h lands in buffer 0
    const float* wr = Wout + o * HID;
    float acc = bout[o];
#pragma unroll 8
    for (int u = 0; u < HID; u++) acc = fmaf(h[u], wr[u], acc);
    out[b * ODIM + o] = acc;
}

// ---------------- launch ----------------
extern "C" void kernel_launch(void* const* d_in, const int* in_sizes, int n_in,
                              void* d_out, int out_size)
{
    (void)in_sizes; (void)n_in; (void)out_size;
    const float* prim = (const float*)d_in[0];
    const float* aux  = (const float*)d_in[1];
    const float* Wih0 = (const float*)d_in[2];
    const float* Whh0 = (const float*)d_in[3];
    const float* bih0 = (const float*)d_in[4];
    const float* bhh0 = (const float*)d_in[5];
    const float* Wih1 = (const float*)d_in[6];
    const float* Whh1 = (const float*)d_in[7];
    const float* bih1 = (const float*)d_in[8];
    const float* bhh1 = (const float*)d_in[9];
    const float* Wout = (const float*)d_in[10];
    const float* bout = (const float*)d_in[11];
    float* out = (float*)d_out;

    prep_kernel<<<1024, 256>>>(prim, aux, Wih0, Whh0, bih0, bhh0, Wih1, Whh1, bih1, bhh1);
    gemm_tf32<<<dim3(16, 256), 256>>>(0);    // x_proj0
    scan_tf32<<<NB_SCAN, NT_SCAN>>>(0);      // layer-0 scan (writes g_h0s)
    gemm_tf32<<<dim3(16, 256), 256>>>(1);    // x_proj1 from h0s
    scan_tf32<<<NB_SCAN, NT_SCAN>>>(1);      // layer-1 scan
    out_kernel<<<BATCH, ODIM>>>(Wout, bout, out);
}